// round 14
// baseline (speedup 1.0000x reference)
#include <cuda_runtime.h>
#include <cstdint>
#include <cstddef>

// Problem constants
constexpr int Bb  = 4;
constexpr int Ss  = 2048;
constexpr int HID = 1024;
constexpr int NH  = 16;
constexpr int HD  = 64;
constexpr float INV_SCALE = 0.125f;      // 1/sqrt(64)

// ---------------------------------------------------------------------------
// Scratch (static device globals — allocation-free at launch time)
// ---------------------------------------------------------------------------
__device__ float g_q  [(size_t)Bb * NH * Ss * HD];   // [b,h,s,d]
__device__ float g_k  [(size_t)Bb * NH * Ss * HD];
__device__ float g_v  [(size_t)Bb * NH * Ss * HD];
__device__ float g_ctx[(size_t)Bb * Ss * NH * HD];   // [b,s,h*64+d]
__device__ float g_scores[(size_t)Bb * NH * Ss * Ss]; // 1 GB

// ---------------------------------------------------------------------------
// tf32 MMA helpers
// ---------------------------------------------------------------------------
__device__ __forceinline__ uint32_t f2tf(float x)
{
    uint32_t u;
    asm("cvt.rna.tf32.f32 %0, %1;" : "=r"(u) : "f"(x));
    return u;
}

// D = A(16x8) * B(8x8) + D, tf32 inputs, f32 accum.
__device__ __forceinline__ void mma8(float* c,
                                     uint32_t a0, uint32_t a1, uint32_t a2, uint32_t a3,
                                     uint32_t b0, uint32_t b1)
{
    asm volatile(
        "mma.sync.aligned.m16n8k8.row.col.f32.tf32.tf32.f32 "
        "{%0,%1,%2,%3},{%4,%5,%6,%7},{%8,%9},{%0,%1,%2,%3};"
        : "+f"(c[0]), "+f"(c[1]), "+f"(c[2]), "+f"(c[3])
        : "r"(a0), "r"(a1), "r"(a2), "r"(a3), "r"(b0), "r"(b1));
}

// Stage a 128(rows) x 32(k) fp32 tile (row-major, leading dim ld) into
// smem[128][36] as tf32 bits. Pad 36 => fragment loads are conflict-free.
__device__ __forceinline__ void stage128(const float* __restrict__ g,
                                         int row0, int k0, int ld,
                                         uint32_t (*sm)[36], int tid)
{
#pragma unroll
    for (int p = 0; p < 4; ++p) {
        int id = tid + p * 256;            // 0..1023 float4 ids
        int r  = id >> 3;                  // 8 float4 per 32-float row
        int c4 = id & 7;
        const float4 f = *reinterpret_cast<const float4*>(
            g + (size_t)(row0 + r) * ld + k0 + c4 * 4);
        sm[r][c4 * 4 + 0] = f2tf(f.x);
        sm[r][c4 * 4 + 1] = f2tf(f.y);
        sm[r][c4 * 4 + 2] = f2tf(f.z);
        sm[r][c4 * 4 + 3] = f2tf(f.w);
    }
}

// Core 128x128 NT tile compute over one staged k32 chunk.
// As: [128][36] (rows=M, cols=k), Bs: [128][36] (rows=N, cols=k).
// Warp grid 4(M) x 2(N); warp tile 32x64; c[2][8][4].
__device__ __forceinline__ void mma_chunk_128x128(const uint32_t (*As)[36],
                                                  const uint32_t (*Bs)[36],
                                                  float c[2][8][4],
                                                  int wm, int wn, int g, int tq)
{
#pragma unroll
    for (int ks = 0; ks < 4; ++ks) {
        const int k8 = ks * 8;
        uint32_t a[2][4];
#pragma unroll
        for (int im = 0; im < 2; ++im) {
            const int m = wm + im * 16;
            a[im][0] = As[m + g    ][k8 + tq    ];
            a[im][1] = As[m + g + 8][k8 + tq    ];
            a[im][2] = As[m + g    ][k8 + tq + 4];
            a[im][3] = As[m + g + 8][k8 + tq + 4];
        }
#pragma unroll
        for (int jn = 0; jn < 8; ++jn) {
            const int n = wn + jn * 8;
            const uint32_t b0 = Bs[n + g][k8 + tq    ];
            const uint32_t b1 = Bs[n + g][k8 + tq + 4];
            mma8(c[0][jn], a[0][0], a[0][1], a[0][2], a[0][3], b0, b1);
            mma8(c[1][jn], a[1][0], a[1][1], a[1][2], a[1][3], b0, b1);
        }
    }
}

// Fast exp on the FMA pipe (x <= 0 in softmax; rel err ~2e-5).
__device__ __forceinline__ float fast_exp(float x)
{
    float t  = fmaxf(x * 1.4426950408889634f, -126.0f);
    float fi = floorf(t);
    float f  = t - fi;
    float p = 1.5357550e-4f;
    p = fmaf(p, f, 1.3333558e-3f);
    p = fmaf(p, f, 9.6181291e-3f);
    p = fmaf(p, f, 5.5504109e-2f);
    p = fmaf(p, f, 2.4022651e-1f);
    p = fmaf(p, f, 6.9314718e-1f);
    p = fmaf(p, f, 1.0f);
    return __int_as_float(((int)fi + 127) << 23) * p;
}

// ---------------------------------------------------------------------------
// Kernel 1: fused QKV projection.  y[b,h,s,d] = x @ W^T + bias
// grid (8, 64, 3), block 256
// ---------------------------------------------------------------------------
__global__ void __launch_bounds__(256, 2)
k_proj(const float* __restrict__ xq, const float* __restrict__ xk,
       const float* __restrict__ xv,
       const float* __restrict__ Wq, const float* __restrict__ Wk,
       const float* __restrict__ Wv,
       const float* __restrict__ bq, const float* __restrict__ bk,
       const float* __restrict__ bv)
{
    __shared__ uint32_t As[128][36];
    __shared__ uint32_t Bs[128][36];

    const int z = blockIdx.z;
    const float* A    = (z == 0) ? xq : (z == 1) ? xk : xv;
    const float* W    = (z == 0) ? Wq : (z == 1) ? Wk : Wv;
    const float* bias = (z == 0) ? bq : (z == 1) ? bk : bv;
    float* out        = (z == 0) ? g_q : (z == 1) ? g_k : g_v;

    const int m0 = blockIdx.y * 128;
    const int n0 = blockIdx.x * 128;
    const int tid  = threadIdx.x;
    const int lane = tid & 31, warp = tid >> 5;
    const int wm = (warp & 3) * 32, wn = (warp >> 2) * 64;
    const int g = lane >> 2, tq = lane & 3;

    float c[2][8][4];
#pragma unroll
    for (int i = 0; i < 2; ++i)
#pragma unroll
        for (int j = 0; j < 8; ++j)
#pragma unroll
            for (int r = 0; r < 4; ++r) c[i][j][r] = 0.f;

    for (int k0 = 0; k0 < HID; k0 += 32) {
        stage128(A, m0, k0, HID, As, tid);
        stage128(W, n0, k0, HID, Bs, tid);
        __syncthreads();
        mma_chunk_128x128(As, Bs, c, wm, wn, g, tq);
        __syncthreads();
    }

#pragma unroll
    for (int jn = 0; jn < 8; ++jn) {
        const int n = n0 + wn + jn * 8 + 2 * tq;   // even; pair stays in one head
        const int h = n >> 6, d = n & 63;
        const float bx = bias[n], by = bias[n + 1];
#pragma unroll
        for (int im = 0; im < 2; ++im) {
            const int m = m0 + wm + im * 16 + g;
            {
                const int bi = m >> 11, s = m & 2047;
                float2 v = { c[im][jn][0] + bx, c[im][jn][1] + by };
                *reinterpret_cast<float2*>(
                    out + (((size_t)(bi * NH + h)) * Ss + s) * HD + d) = v;
            }
            {
                const int m2 = m + 8;
                const int bi = m2 >> 11, s = m2 & 2047;
                float2 v = { c[im][jn][2] + bx, c[im][jn][3] + by };
                *reinterpret_cast<float2*>(
                    out + (((size_t)(bi * NH + h)) * Ss + s) * HD + d) = v;
            }
        }
    }
}

// ---------------------------------------------------------------------------
// Kernel 2: scores = Q·K^T / sqrt(d) (+mask), per (b,h)
// grid (16,16,64), block 256
// ---------------------------------------------------------------------------
__global__ void __launch_bounds__(256, 2)
k_scores(const unsigned char* __restrict__ mask)
{
    __shared__ uint32_t As[128][36];
    __shared__ uint32_t Bs[128][36];

    const int bh = blockIdx.z;
    const float* Q = g_q + (size_t)bh * Ss * HD;
    const float* K = g_k + (size_t)bh * Ss * HD;
    float* Sout    = g_scores + (size_t)bh * Ss * Ss;
    const int bi   = bh >> 4;

    const int m0 = blockIdx.y * 128;
    const int n0 = blockIdx.x * 128;
    const int tid  = threadIdx.x;
    const int lane = tid & 31, warp = tid >> 5;
    const int wm = (warp & 3) * 32, wn = (warp >> 2) * 64;
    const int g = lane >> 2, tq = lane & 3;

    float c[2][8][4];
#pragma unroll
    for (int i = 0; i < 2; ++i)
#pragma unroll
        for (int j = 0; j < 8; ++j)
#pragma unroll
            for (int r = 0; r < 4; ++r) c[i][j][r] = 0.f;

#pragma unroll
    for (int k0 = 0; k0 < HD; k0 += 32) {
        stage128(Q, m0, k0, HD, As, tid);
        stage128(K, n0, k0, HD, Bs, tid);
        __syncthreads();
        mma_chunk_128x128(As, Bs, c, wm, wn, g, tq);
        __syncthreads();
    }

#pragma unroll
    for (int jn = 0; jn < 8; ++jn) {
        const int n = n0 + wn + jn * 8 + 2 * tq;
#pragma unroll
        for (int im = 0; im < 2; ++im) {
#pragma unroll
            for (int rr = 0; rr < 2; ++rr) {
                const int m = m0 + wm + im * 16 + g + rr * 8;
                const size_t mrow = (size_t)(bi * Ss + m) * Ss + n;
                float v0 = c[im][jn][rr * 2 + 0] * INV_SCALE;
                float v1 = c[im][jn][rr * 2 + 1] * INV_SCALE;
                if (mask[mrow])     v0 = -1e9f;
                if (mask[mrow + 1]) v1 = -1e9f;
                *reinterpret_cast<float2*>(Sout + (size_t)m * Ss + n) =
                    make_float2(v0, v1);
            }
        }
    }
}

// ---------------------------------------------------------------------------
// Kernel 3: row softmax in place; write head-0 attn to top_attn
// grid (B*NH*S = 131072), block 256; each thread owns 8 elements
// ---------------------------------------------------------------------------
__global__ void __launch_bounds__(256)
k_softmax(float* __restrict__ top)
{
    const size_t row = blockIdx.x;
    float* p = g_scores + row * Ss;
    const int tid = threadIdx.x;

    float4* p4 = reinterpret_cast<float4*>(p);
    float4 v0 = p4[tid];
    float4 v1 = p4[tid + 256];

    float mx = fmaxf(fmaxf(fmaxf(v0.x, v0.y), fmaxf(v0.z, v0.w)),
                     fmaxf(fmaxf(v1.x, v1.y), fmaxf(v1.z, v1.w)));
#pragma unroll
    for (int o = 16; o > 0; o >>= 1)
        mx = fmaxf(mx, __shfl_xor_sync(0xffffffffu, mx, o));

    __shared__ float smax[8];
    __shared__ float ssum[8];
    if ((tid & 31) == 0) smax[tid >> 5] = mx;
    __syncthreads();
    float bm = smax[0];
#pragma unroll
    for (int i = 1; i < 8; ++i) bm = fmaxf(bm, smax[i]);

    v0.x = fast_exp(v0.x - bm); v0.y = fast_exp(v0.y - bm);
    v0.z = fast_exp(v0.z - bm); v0.w = fast_exp(v0.w - bm);
    v1.x = fast_exp(v1.x - bm); v1.y = fast_exp(v1.y - bm);
    v1.z = fast_exp(v1.z - bm); v1.w = fast_exp(v1.w - bm);

    float s = (v0.x + v0.y) + (v0.z + v0.w) + (v1.x + v1.y) + (v1.z + v1.w);
#pragma unroll
    for (int o = 16; o > 0; o >>= 1)
        s += __shfl_xor_sync(0xffffffffu, s, o);
    if ((tid & 31) == 0) ssum[tid >> 5] = s;
    __syncthreads();
    float tot = 0.f;
#pragma unroll
    for (int i = 0; i < 8; ++i) tot += ssum[i];
    const float inv = 1.0f / tot;

    v0.x *= inv; v0.y *= inv; v0.z *= inv; v0.w *= inv;
    v1.x *= inv; v1.y *= inv; v1.z *= inv; v1.w *= inv;

    p4[tid]       = v0;
    p4[tid + 256] = v1;

    const int h = (int)((row >> 11) & 15);
    if (h == 0) {
        const size_t bi = row >> 15;
        const size_t sq = row & 2047;
        float4* t4 = reinterpret_cast<float4*>(top + (bi * Ss + sq) * Ss);
        t4[tid]       = v0;
        t4[tid + 256] = v1;
    }
}

// ---------------------------------------------------------------------------
// Kernel 4: context = attn @ V, per (b,h); output -> g_ctx [b,s,h*64+d]
// grid (16, 1, 64), block 256; block tile 128(M) x 64(N), k32 chunks
// Warp grid 4(M) x 2(N); warp tile 32x32; c[2][4][4].
// ---------------------------------------------------------------------------
__global__ void __launch_bounds__(256, 2)
k_context()
{
    __shared__ uint32_t As[128][36];
    __shared__ uint32_t Vs[64][36];     // [n=d][k] (transposed V tile)

    const int bh = blockIdx.z;
    const float* Amat = g_scores + (size_t)bh * Ss * Ss;
    const float* Vmat = g_v + (size_t)bh * Ss * HD;

    const int m0 = blockIdx.x * 128;
    const int tid  = threadIdx.x;
    const int lane = tid & 31, warp = tid >> 5;
    const int wm = (warp & 3) * 32, wn = (warp >> 2) * 32;
    const int g = lane >> 2, tq = lane & 3;

    float c[2][4][4];
#pragma unroll
    for (int i = 0; i < 2; ++i)
#pragma unroll
        for (int j = 0; j < 4; ++j)
#pragma unroll
            for (int r = 0; r < 4; ++r) c[i][j][r] = 0.f;

    for (int k0 = 0; k0 < Ss; k0 += 32) {
        stage128(Amat, m0, k0, Ss, As, tid);
        // V tile 32(k) x 64(n) -> Vs[n][k] transposed, tf32
#pragma unroll
        for (int p = 0; p < 2; ++p) {
            int id = tid + p * 256;        // 0..511 float4 ids
            int k  = id >> 4;              // 16 float4 per 64-wide row
            int c4 = id & 15;
            float4 f = *reinterpret_cast<const float4*>(
                Vmat + (size_t)(k0 + k) * HD + c4 * 4);
            Vs[c4 * 4 + 0][k] = f2tf(f.x);
            Vs[c4 * 4 + 1][k] = f2tf(f.y);
            Vs[c4 * 4 + 2][k] = f2tf(f.z);
            Vs[c4 * 4 + 3][k] = f2tf(f.w);
        }
        __syncthreads();

#pragma unroll
        for (int ks = 0; ks < 4; ++ks) {
            const int k8 = ks * 8;
            uint32_t a[2][4];
#pragma unroll
            for (int im = 0; im < 2; ++im) {
                const int m = wm + im * 16;
                a[im][0] = As[m + g    ][k8 + tq    ];
                a[im][1] = As[m + g + 8][k8 + tq    ];
                a[im][2] = As[m + g    ][k8 + tq + 4];
                a[im][3] = As[m + g + 8][k8 + tq + 4];
            }
#pragma unroll
            for (int jn = 0; jn < 4; ++jn) {
                const int n = wn + jn * 8;
                const uint32_t b0 = Vs[n + g][k8 + tq    ];
                const uint32_t b1 = Vs[n + g][k8 + tq + 4];
                mma8(c[0][jn], a[0][0], a[0][1], a[0][2], a[0][3], b0, b1);
                mma8(c[1][jn], a[1][0], a[1][1], a[1][2], a[1][3], b0, b1);
            }
        }
        __syncthreads();
    }

    const int bi = bh >> 4, h = bh & 15;
#pragma unroll
    for (int jn = 0; jn < 4; ++jn) {
        const int d = wn + jn * 8 + 2 * tq;
#pragma unroll
        for (int im = 0; im < 2; ++im) {
#pragma unroll
            for (int rr = 0; rr < 2; ++rr) {
                const int sq = m0 + wm + im * 16 + g + rr * 8;
                *reinterpret_cast<float2*>(
                    g_ctx + ((size_t)(bi * Ss + sq)) * (NH * HD) + h * HD + d) =
                    make_float2(c[im][jn][rr * 2], c[im][jn][rr * 2 + 1]);
            }
        }
    }
}

// ---------------------------------------------------------------------------
// Kernel 5: output = ctx @ W_o^T + b_o  -> d_out[0 : B*S*HID)
// grid (8, 64), block 256
// ---------------------------------------------------------------------------
__global__ void __launch_bounds__(256, 2)
k_outproj(const float* __restrict__ Wo, const float* __restrict__ bo,
          float* __restrict__ out)
{
    __shared__ uint32_t As[128][36];
    __shared__ uint32_t Bs[128][36];

    const int m0 = blockIdx.y * 128;
    const int n0 = blockIdx.x * 128;
    const int tid  = threadIdx.x;
    const int lane = tid & 31, warp = tid >> 5;
    const int wm = (warp & 3) * 32, wn = (warp >> 2) * 64;
    const int g = lane >> 2, tq = lane & 3;

    float c[2][8][4];
#pragma unroll
    for (int i = 0; i < 2; ++i)
#pragma unroll
        for (int j = 0; j < 8; ++j)
#pragma unroll
            for (int r = 0; r < 4; ++r) c[i][j][r] = 0.f;

    for (int k0 = 0; k0 < NH * HD; k0 += 32) {
        stage128(g_ctx, m0, k0, NH * HD, As, tid);
        stage128(Wo,   n0, k0, NH * HD, Bs, tid);
        __syncthreads();
        mma_chunk_128x128(As, Bs, c, wm, wn, g, tq);
        __syncthreads();
    }

#pragma unroll
    for (int jn = 0; jn < 8; ++jn) {
        const int n = n0 + wn + jn * 8 + 2 * tq;
        const float bx = bo[n], by = bo[n + 1];
#pragma unroll
        for (int im = 0; im < 2; ++im) {
#pragma unroll
            for (int rr = 0; rr < 2; ++rr) {
                const int m = m0 + wm + im * 16 + g + rr * 8;
                *reinterpret_cast<float2*>(out + (size_t)m * HID + n) =
                    make_float2(c[im][jn][rr * 2] + bx, c[im][jn][rr * 2 + 1] + by);
            }
        }
    }
}

// ---------------------------------------------------------------------------
// Launch
// ---------------------------------------------------------------------------
extern "C" void kernel_launch(void* const* d_in, const int* in_sizes, int n_in,
                              void* d_out, int out_size)
{
    (void)in_sizes; (void)n_in; (void)out_size;
    const float* q  = (const float*)d_in[0];
    const float* k  = (const float*)d_in[1];
    const float* v  = (const float*)d_in[2];
    const unsigned char* mask = (const unsigned char*)d_in[3];
    const float* Wq = (const float*)d_in[4];
    const float* bq = (const float*)d_in[5];
    const float* Wk = (const float*)d_in[6];
    const float* bk = (const float*)d_in[7];
    const float* Wv = (const float*)d_in[8];
    const float* bv = (const float*)d_in[9];
    const float* Wo = (const float*)d_in[10];
    const float* bo = (const float*)d_in[11];

    float* out = (float*)d_out;
    float* top = out + (size_t)Bb * Ss * HID;   // top_attn region

    k_proj   <<<dim3(8, 64, 3), 256>>>(q, k, v, Wq, Wk, Wv, bq, bk, bv);
    k_scores <<<dim3(16, 16, 64), 256>>>(mask);
    k_softmax<<<Bb * NH * Ss, 256>>>(top);
    k_context<<<dim3(16, 1, 64), 256>>>();
    k_outproj<<<dim3(8, 64), 256>>>(Wo, bo, out);
}

// round 15
// speedup vs baseline: 1.3447x; 1.3447x over previous
#include <cuda_runtime.h>
#include <cstdint>
#include <cstddef>

// Problem constants
constexpr int Bb  = 4;
constexpr int Ss  = 2048;
constexpr int HID = 1024;
constexpr int NH  = 16;
constexpr int HD  = 64;
constexpr float INV_SCALE = 0.125f;      // 1/sqrt(64)

// ---------------------------------------------------------------------------
// Scratch (static device globals — allocation-free at launch time)
// ---------------------------------------------------------------------------
__device__ float g_q  [(size_t)Bb * NH * Ss * HD];   // [b,h,s,d]
__device__ float g_k  [(size_t)Bb * NH * Ss * HD];
__device__ float g_v  [(size_t)Bb * NH * Ss * HD];
__device__ float g_vt [(size_t)Bb * NH * HD * Ss];   // [b,h,d,s]  (V transposed)
__device__ float g_ctx[(size_t)Bb * Ss * NH * HD];   // [b,s,h*64+d]

// ---------------------------------------------------------------------------
// tf32 MMA helpers
// ---------------------------------------------------------------------------
__device__ __forceinline__ uint32_t f2tf(float x)
{
    uint32_t u;
    asm("cvt.rna.tf32.f32 %0, %1;" : "=r"(u) : "f"(x));
    return u;
}

// D = A(16x8) * B(8x8) + D, tf32 inputs, f32 accum.
__device__ __forceinline__ void mma8(float* c,
                                     uint32_t a0, uint32_t a1, uint32_t a2, uint32_t a3,
                                     uint32_t b0, uint32_t b1)
{
    asm volatile(
        "mma.sync.aligned.m16n8k8.row.col.f32.tf32.tf32.f32 "
        "{%0,%1,%2,%3},{%4,%5,%6,%7},{%8,%9},{%0,%1,%2,%3};"
        : "+f"(c[0]), "+f"(c[1]), "+f"(c[2]), "+f"(c[3])
        : "r"(a0), "r"(a1), "r"(a2), "r"(a3), "r"(b0), "r"(b1));
}

// Legacy staging (k_proj / k_scores_h0 / k_outproj): rows x 32 tile, pad 36.
__device__ __forceinline__ void stage128(const float* __restrict__ g,
                                         int row0, int k0, int ld,
                                         uint32_t (*sm)[36], int tid)
{
#pragma unroll
    for (int p = 0; p < 4; ++p) {
        int id = tid + p * 256;
        int r  = id >> 3;
        int c4 = id & 7;
        const float4 f = *reinterpret_cast<const float4*>(
            g + (size_t)(row0 + r) * ld + k0 + c4 * 4);
        sm[r][c4 * 4 + 0] = f2tf(f.x);
        sm[r][c4 * 4 + 1] = f2tf(f.y);
        sm[r][c4 * 4 + 2] = f2tf(f.z);
        sm[r][c4 * 4 + 3] = f2tf(f.w);
    }
}

// Flash staging: ROWS x 64 tile, stride 72, k-columns permuted within each
// 8-group as [0,4,1,5,2,6,3,7] so fragment pairs (tq, tq+4) are adjacent
// (single LDS.64, conflict-free with stride ≡ 8 mod 32).
template<int ROWS>
__device__ __forceinline__ void stage_perm(const float* __restrict__ g,
                                           int row0, int ld,
                                           uint32_t (*sm)[72], int tid)
{
#pragma unroll
    for (int p = 0; p < ROWS / 16; ++p) {
        int id = tid + p * 256;
        int r  = id >> 4;                // 16 float4 per 64-wide row
        int c4 = id & 15;
        const float4 f = *reinterpret_cast<const float4*>(
            g + (size_t)(row0 + r) * ld + c4 * 4);
        const int base = ((4 * c4) & 56) + (c4 & 1);  // perm position of col 4*c4
        uint32_t* row = sm[r];
        row[base + 0] = f2tf(f.x);
        row[base + 2] = f2tf(f.y);
        row[base + 4] = f2tf(f.z);
        row[base + 6] = f2tf(f.w);
    }
}

// Core 128x128 NT tile compute (legacy kernels). As/Bs [128][36].
__device__ __forceinline__ void mma_chunk_128x128(const uint32_t (*As)[36],
                                                  const uint32_t (*Bs)[36],
                                                  float c[2][8][4],
                                                  int wm, int wn, int g, int tq)
{
#pragma unroll
    for (int ks = 0; ks < 4; ++ks) {
        const int k8 = ks * 8;
        uint32_t a[2][4];
#pragma unroll
        for (int im = 0; im < 2; ++im) {
            const int m = wm + im * 16;
            a[im][0] = As[m + g    ][k8 + tq    ];
            a[im][1] = As[m + g + 8][k8 + tq    ];
            a[im][2] = As[m + g    ][k8 + tq + 4];
            a[im][3] = As[m + g + 8][k8 + tq + 4];
        }
#pragma unroll
        for (int jn = 0; jn < 8; ++jn) {
            const int n = wn + jn * 8;
            const uint32_t b0 = Bs[n + g][k8 + tq    ];
            const uint32_t b1 = Bs[n + g][k8 + tq + 4];
            mma8(c[0][jn], a[0][0], a[0][1], a[0][2], a[0][3], b0, b1);
            mma8(c[1][jn], a[1][0], a[1][1], a[1][2], a[1][3], b0, b1);
        }
    }
}

// Fast exp on the FMA pipe (x <= 0 in softmax; rel err ~2e-5).
__device__ __forceinline__ float fast_exp(float x)
{
    float t  = fmaxf(x * 1.4426950408889634f, -126.0f);
    float fi = floorf(t);
    float f  = t - fi;
    float p = 1.5357550e-4f;
    p = fmaf(p, f, 1.3333558e-3f);
    p = fmaf(p, f, 9.6181291e-3f);
    p = fmaf(p, f, 5.5504109e-2f);
    p = fmaf(p, f, 2.4022651e-1f);
    p = fmaf(p, f, 6.9314718e-1f);
    p = fmaf(p, f, 1.0f);
    return __int_as_float(((int)fi + 127) << 23) * p;
}

// ---------------------------------------------------------------------------
// Kernel 1: fused QKV projection.  y[b,h,s,d] = x @ W^T + bias
// grid (8, 64, 3), block 256
// ---------------------------------------------------------------------------
__global__ void __launch_bounds__(256, 2)
k_proj(const float* __restrict__ xq, const float* __restrict__ xk,
       const float* __restrict__ xv,
       const float* __restrict__ Wq, const float* __restrict__ Wk,
       const float* __restrict__ Wv,
       const float* __restrict__ bq, const float* __restrict__ bk,
       const float* __restrict__ bv)
{
    __shared__ uint32_t As[128][36];
    __shared__ uint32_t Bs[128][36];

    const int z = blockIdx.z;
    const float* A    = (z == 0) ? xq : (z == 1) ? xk : xv;
    const float* W    = (z == 0) ? Wq : (z == 1) ? Wk : Wv;
    const float* bias = (z == 0) ? bq : (z == 1) ? bk : bv;
    float* out        = (z == 0) ? g_q : (z == 1) ? g_k : g_v;

    const int m0 = blockIdx.y * 128;
    const int n0 = blockIdx.x * 128;
    const int tid  = threadIdx.x;
    const int lane = tid & 31, warp = tid >> 5;
    const int wm = (warp & 3) * 32, wn = (warp >> 2) * 64;
    const int g = lane >> 2, tq = lane & 3;

    float c[2][8][4];
#pragma unroll
    for (int i = 0; i < 2; ++i)
#pragma unroll
        for (int j = 0; j < 8; ++j)
#pragma unroll
            for (int r = 0; r < 4; ++r) c[i][j][r] = 0.f;

    for (int k0 = 0; k0 < HID; k0 += 32) {
        stage128(A, m0, k0, HID, As, tid);
        stage128(W, n0, k0, HID, Bs, tid);
        __syncthreads();
        mma_chunk_128x128(As, Bs, c, wm, wn, g, tq);
        __syncthreads();
    }

#pragma unroll
    for (int jn = 0; jn < 8; ++jn) {
        const int n = n0 + wn + jn * 8 + 2 * tq;
        const int h = n >> 6, d = n & 63;
        const float bx = bias[n], by = bias[n + 1];
#pragma unroll
        for (int im = 0; im < 2; ++im) {
            const int m = m0 + wm + im * 16 + g;
            {
                const int bi = m >> 11, s = m & 2047;
                float2 v = { c[im][jn][0] + bx, c[im][jn][1] + by };
                *reinterpret_cast<float2*>(
                    out + (((size_t)(bi * NH + h)) * Ss + s) * HD + d) = v;
            }
            {
                const int m2 = m + 8;
                const int bi = m2 >> 11, s = m2 & 2047;
                float2 v = { c[im][jn][2] + bx, c[im][jn][3] + by };
                *reinterpret_cast<float2*>(
                    out + (((size_t)(bi * NH + h)) * Ss + s) * HD + d) = v;
            }
        }
    }
}

// ---------------------------------------------------------------------------
// Kernel 2: V transpose  g_v[b,h,s,d] -> g_vt[b,h,d,s]
// grid (32, 64), block 256
// ---------------------------------------------------------------------------
__global__ void __launch_bounds__(256)
k_vtrans()
{
    __shared__ float T[64][65];
    const int bh = blockIdx.y;
    const int s0 = blockIdx.x * 64;
    const float* src = g_v + ((size_t)bh * Ss + s0) * HD;
    const int tid = threadIdx.x;

#pragma unroll
    for (int p = 0; p < 4; ++p) {
        int id = tid + p * 256;
        int r  = id >> 4, c4 = id & 15;
        float4 f = *reinterpret_cast<const float4*>(src + (size_t)r * HD + c4 * 4);
        T[r][c4 * 4 + 0] = f.x; T[r][c4 * 4 + 1] = f.y;
        T[r][c4 * 4 + 2] = f.z; T[r][c4 * 4 + 3] = f.w;
    }
    __syncthreads();

    float* dst = g_vt + (size_t)bh * HD * Ss + s0;
#pragma unroll
    for (int p = 0; p < 4; ++p) {
        int id = tid + p * 256;
        int d  = id >> 4, c4 = id & 15;
        float4 o;
        o.x = T[c4 * 4 + 0][d]; o.y = T[c4 * 4 + 1][d];
        o.z = T[c4 * 4 + 2][d]; o.w = T[c4 * 4 + 3][d];
        *reinterpret_cast<float4*>(dst + (size_t)d * Ss + c4 * 4) = o;
    }
}

// ---------------------------------------------------------------------------
// Kernel 3: flash attention (scores+softmax+context fused), all 64 bh.
// grid (16 q-tiles, 64 bh), block 256 (8 warps, warp tile 16x64).
// Dynamic smem: Qs[128][72] Ks[64][72] Vt[64][72] Ps[128][72] = 110592 B.
// ---------------------------------------------------------------------------
constexpr int FLASH_SMEM_BYTES = (9216 + 4608 + 4608 + 9216) * 4;

__global__ void __launch_bounds__(256, 2)
k_flash(const unsigned char* __restrict__ mask)
{
    extern __shared__ uint32_t smemw[];
    uint32_t (*Qs)[72] = reinterpret_cast<uint32_t(*)[72]>(smemw);
    uint32_t (*Ks)[72] = reinterpret_cast<uint32_t(*)[72]>(smemw + 9216);
    uint32_t (*Vt)[72] = reinterpret_cast<uint32_t(*)[72]>(smemw + 13824);
    uint32_t (*Ps)[72] = reinterpret_cast<uint32_t(*)[72]>(smemw + 18432);

    const int bh = blockIdx.y;
    const int bi = bh >> 4, h = bh & 15;
    const int m0 = blockIdx.x * 128;
    const float* Q  = g_q  + (size_t)bh * Ss * HD;
    const float* K  = g_k  + (size_t)bh * Ss * HD;
    const float* VT = g_vt + (size_t)bh * HD * Ss;

    const int tid  = threadIdx.x;
    const int lane = tid & 31, warp = tid >> 5;
    const int wm = warp * 16;
    const int g = lane >> 2, tq = lane & 3;
    // permuted positions of kv-columns 2tq and 2tq+1 within an 8-group
    const int pe = ((2 * tq) & 3) * 2 + ((2 * tq) >> 2);
    const int po = ((2 * tq + 1) & 3) * 2 + ((2 * tq + 1) >> 2);

    stage_perm<128>(Q, m0, HD, Qs, tid);

    float co[8][4];
#pragma unroll
    for (int j = 0; j < 8; ++j)
#pragma unroll
        for (int r = 0; r < 4; ++r) co[j][r] = 0.f;
    float mr0 = -3.0e38f, mr1 = -3.0e38f, lr0 = 0.f, lr1 = 0.f;

    const unsigned char* mbase0 =
        mask + ((size_t)bi * Ss + (m0 + wm + g)) * Ss;
    const unsigned char* mbase1 = mbase0 + (size_t)8 * Ss;

    for (int it = 0; it < Ss / 64; ++it) {
        const int kv0 = it * 64;
        __syncthreads();                       // prev PV reads done
        stage_perm<64>(K, kv0, HD, Ks, tid);
        stage_perm<64>(VT + kv0, 0, Ss, Vt, tid);
        __syncthreads();

        // ---- S = Q K^T over this kv tile ----
        float cs[8][4];
#pragma unroll
        for (int j = 0; j < 8; ++j)
#pragma unroll
            for (int r = 0; r < 4; ++r) cs[j][r] = 0.f;

#pragma unroll
        for (int ks = 0; ks < 8; ++ks) {
            const int kp = ks * 8 + 2 * tq;
            const uint2 a0 = *reinterpret_cast<const uint2*>(&Qs[wm + g    ][kp]);
            const uint2 a1 = *reinterpret_cast<const uint2*>(&Qs[wm + g + 8][kp]);
#pragma unroll
            for (int jn = 0; jn < 8; ++jn) {
                const uint2 bb = *reinterpret_cast<const uint2*>(&Ks[jn * 8 + g][kp]);
                mma8(cs[jn], a0.x, a1.x, a0.y, a1.y, bb.x, bb.y);
            }
        }

        // ---- scale + mask + row max ----
        float mx0 = -3.0e38f, mx1 = -3.0e38f;
#pragma unroll
        for (int jn = 0; jn < 8; ++jn) {
            const int n = kv0 + jn * 8 + 2 * tq;
            const uchar2 u0 = *reinterpret_cast<const uchar2*>(mbase0 + n);
            const uchar2 u1 = *reinterpret_cast<const uchar2*>(mbase1 + n);
            float v0 = cs[jn][0] * INV_SCALE; if (u0.x) v0 = -1e9f;
            float v1 = cs[jn][1] * INV_SCALE; if (u0.y) v1 = -1e9f;
            float v2 = cs[jn][2] * INV_SCALE; if (u1.x) v2 = -1e9f;
            float v3 = cs[jn][3] * INV_SCALE; if (u1.y) v3 = -1e9f;
            cs[jn][0] = v0; cs[jn][1] = v1; cs[jn][2] = v2; cs[jn][3] = v3;
            mx0 = fmaxf(mx0, fmaxf(v0, v1));
            mx1 = fmaxf(mx1, fmaxf(v2, v3));
        }
        mx0 = fmaxf(mx0, __shfl_xor_sync(0xffffffffu, mx0, 1));
        mx0 = fmaxf(mx0, __shfl_xor_sync(0xffffffffu, mx0, 2));
        mx1 = fmaxf(mx1, __shfl_xor_sync(0xffffffffu, mx1, 1));
        mx1 = fmaxf(mx1, __shfl_xor_sync(0xffffffffu, mx1, 2));

        const float mn0 = fmaxf(mr0, mx0), mn1 = fmaxf(mr1, mx1);
        const float al0 = fast_exp(mr0 - mn0), al1 = fast_exp(mr1 - mn1);
        mr0 = mn0; mr1 = mn1;

        // ---- P = exp(S - m), store permuted to smem; rescale O ----
        float s0 = 0.f, s1 = 0.f;
#pragma unroll
        for (int jn = 0; jn < 8; ++jn) {
            const float p0 = fast_exp(cs[jn][0] - mn0);
            const float p1 = fast_exp(cs[jn][1] - mn0);
            const float p2 = fast_exp(cs[jn][2] - mn1);
            const float p3 = fast_exp(cs[jn][3] - mn1);
            s0 += p0 + p1; s1 += p2 + p3;
            uint32_t* r0 = Ps[wm + g    ] + jn * 8;
            uint32_t* r1 = Ps[wm + g + 8] + jn * 8;
            r0[pe] = f2tf(p0); r0[po] = f2tf(p1);
            r1[pe] = f2tf(p2); r1[po] = f2tf(p3);
            co[jn][0] *= al0; co[jn][1] *= al0;
            co[jn][2] *= al1; co[jn][3] *= al1;
        }
        s0 += __shfl_xor_sync(0xffffffffu, s0, 1);
        s0 += __shfl_xor_sync(0xffffffffu, s0, 2);
        s1 += __shfl_xor_sync(0xffffffffu, s1, 1);
        s1 += __shfl_xor_sync(0xffffffffu, s1, 2);
        lr0 = lr0 * al0 + s0;
        lr1 = lr1 * al1 + s1;

        __syncwarp();   // P rows are warp-private; smem visibility within warp

        // ---- O += P V ----
#pragma unroll
        for (int ks = 0; ks < 8; ++ks) {
            const int kp = ks * 8 + 2 * tq;
            const uint2 a0 = *reinterpret_cast<const uint2*>(&Ps[wm + g    ][kp]);
            const uint2 a1 = *reinterpret_cast<const uint2*>(&Ps[wm + g + 8][kp]);
#pragma unroll
            for (int jn = 0; jn < 8; ++jn) {
                const uint2 bb = *reinterpret_cast<const uint2*>(&Vt[jn * 8 + g][kp]);
                mma8(co[jn], a0.x, a1.x, a0.y, a1.y, bb.x, bb.y);
            }
        }
    }

    // ---- finalize: O /= l, write to g_ctx ----
    const float i0 = 1.f / lr0, i1 = 1.f / lr1;
    float* C0 = g_ctx + ((size_t)(bi * Ss + m0 + wm + g)) * (NH * HD) + h * HD;
    float* C1 = C0 + (size_t)8 * (NH * HD);
#pragma unroll
    for (int jn = 0; jn < 8; ++jn) {
        const int d = jn * 8 + 2 * tq;
        *reinterpret_cast<float2*>(C0 + d) =
            make_float2(co[jn][0] * i0, co[jn][1] * i0);
        *reinterpret_cast<float2*>(C1 + d) =
            make_float2(co[jn][2] * i1, co[jn][3] * i1);
    }
}

// ---------------------------------------------------------------------------
// Kernel 4: head-0 scores -> top buffer (raw, scaled+masked)
// grid (16, 16, 4), block 256
// ---------------------------------------------------------------------------
__global__ void __launch_bounds__(256, 2)
k_scores_h0(const unsigned char* __restrict__ mask, float* __restrict__ topbase)
{
    __shared__ uint32_t As[128][36];
    __shared__ uint32_t Bs[128][36];

    const int bi = blockIdx.z;
    const int bh = bi * NH;                 // head 0 of batch bi
    const float* Q = g_q + (size_t)bh * Ss * HD;
    const float* K = g_k + (size_t)bh * Ss * HD;
    float* Sout    = topbase + (size_t)bi * Ss * Ss;

    const int m0 = blockIdx.y * 128;
    const int n0 = blockIdx.x * 128;
    const int tid  = threadIdx.x;
    const int lane = tid & 31, warp = tid >> 5;
    const int wm = (warp & 3) * 32, wn = (warp >> 2) * 64;
    const int g = lane >> 2, tq = lane & 3;

    float c[2][8][4];
#pragma unroll
    for (int i = 0; i < 2; ++i)
#pragma unroll
        for (int j = 0; j < 8; ++j)
#pragma unroll
            for (int r = 0; r < 4; ++r) c[i][j][r] = 0.f;

#pragma unroll
    for (int k0 = 0; k0 < HD; k0 += 32) {
        stage128(Q, m0, k0, HD, As, tid);
        stage128(K, n0, k0, HD, Bs, tid);
        __syncthreads();
        mma_chunk_128x128(As, Bs, c, wm, wn, g, tq);
        __syncthreads();
    }

#pragma unroll
    for (int jn = 0; jn < 8; ++jn) {
        const int n = n0 + wn + jn * 8 + 2 * tq;
#pragma unroll
        for (int im = 0; im < 2; ++im) {
#pragma unroll
            for (int rr = 0; rr < 2; ++rr) {
                const int m = m0 + wm + im * 16 + g + rr * 8;
                const size_t mrow = (size_t)(bi * Ss + m) * Ss + n;
                float v0 = c[im][jn][rr * 2 + 0] * INV_SCALE;
                float v1 = c[im][jn][rr * 2 + 1] * INV_SCALE;
                if (mask[mrow])     v0 = -1e9f;
                if (mask[mrow + 1]) v1 = -1e9f;
                *reinterpret_cast<float2*>(Sout + (size_t)m * Ss + n) =
                    make_float2(v0, v1);
            }
        }
    }
}

// ---------------------------------------------------------------------------
// Kernel 5: softmax in place over top buffer rows (4*2048 rows)
// ---------------------------------------------------------------------------
__global__ void __launch_bounds__(256)
k_softmax_h0(float* __restrict__ top)
{
    const size_t row = blockIdx.x;
    float* p = top + row * Ss;
    const int tid = threadIdx.x;

    float4* p4 = reinterpret_cast<float4*>(p);
    float4 v0 = p4[tid];
    float4 v1 = p4[tid + 256];

    float mx = fmaxf(fmaxf(fmaxf(v0.x, v0.y), fmaxf(v0.z, v0.w)),
                     fmaxf(fmaxf(v1.x, v1.y), fmaxf(v1.z, v1.w)));
#pragma unroll
    for (int o = 16; o > 0; o >>= 1)
        mx = fmaxf(mx, __shfl_xor_sync(0xffffffffu, mx, o));

    __shared__ float smax[8];
    __shared__ float ssum[8];
    if ((tid & 31) == 0) smax[tid >> 5] = mx;
    __syncthreads();
    float bm = smax[0];
#pragma unroll
    for (int i = 1; i < 8; ++i) bm = fmaxf(bm, smax[i]);

    v0.x = fast_exp(v0.x - bm); v0.y = fast_exp(v0.y - bm);
    v0.z = fast_exp(v0.z - bm); v0.w = fast_exp(v0.w - bm);
    v1.x = fast_exp(v1.x - bm); v1.y = fast_exp(v1.y - bm);
    v1.z = fast_exp(v1.z - bm); v1.w = fast_exp(v1.w - bm);

    float s = (v0.x + v0.y) + (v0.z + v0.w) + (v1.x + v1.y) + (v1.z + v1.w);
#pragma unroll
    for (int o = 16; o > 0; o >>= 1)
        s += __shfl_xor_sync(0xffffffffu, s, o);
    if ((tid & 31) == 0) ssum[tid >> 5] = s;
    __syncthreads();
    float tot = 0.f;
#pragma unroll
    for (int i = 0; i < 8; ++i) tot += ssum[i];
    const float inv = 1.0f / tot;

    v0.x *= inv; v0.y *= inv; v0.z *= inv; v0.w *= inv;
    v1.x *= inv; v1.y *= inv; v1.z *= inv; v1.w *= inv;

    p4[tid]       = v0;
    p4[tid + 256] = v1;
}

// ---------------------------------------------------------------------------
// Kernel 6: output = ctx @ W_o^T + b_o  -> d_out[0 : B*S*HID)
// grid (8, 64), block 256
// ---------------------------------------------------------------------------
__global__ void __launch_bounds__(256, 2)
k_outproj(const float* __restrict__ Wo, const float* __restrict__ bo,
          float* __restrict__ out)
{
    __shared__ uint32_t As[128][36];
    __shared__ uint32_t Bs[128][36];

    const int m0 = blockIdx.y * 128;
    const int n0 = blockIdx.x * 128;
    const int tid  = threadIdx.x;
    const int lane = tid & 31, warp = tid >> 5;
    const int wm = (warp & 3) * 32, wn = (warp >> 2) * 64;
    const int g = lane >> 2, tq = lane & 3;

    float c[2][8][4];
#pragma unroll
    for (int i = 0; i < 2; ++i)
#pragma unroll
        for (int j = 0; j < 8; ++j)
#pragma unroll
            for (int r = 0; r < 4; ++r) c[i][j][r] = 0.f;

    for (int k0 = 0; k0 < NH * HD; k0 += 32) {
        stage128(g_ctx, m0, k0, NH * HD, As, tid);
        stage128(Wo,   n0, k0, NH * HD, Bs, tid);
        __syncthreads();
        mma_chunk_128x128(As, Bs, c, wm, wn, g, tq);
        __syncthreads();
    }

#pragma unroll
    for (int jn = 0; jn < 8; ++jn) {
        const int n = n0 + wn + jn * 8 + 2 * tq;
        const float bx = bo[n], by = bo[n + 1];
#pragma unroll
        for (int im = 0; im < 2; ++im) {
#pragma unroll
            for (int rr = 0; rr < 2; ++rr) {
                const int m = m0 + wm + im * 16 + g + rr * 8;
                *reinterpret_cast<float2*>(out + (size_t)m * HID + n) =
                    make_float2(c[im][jn][rr * 2] + bx, c[im][jn][rr * 2 + 1] + by);
            }
        }
    }
}

// ---------------------------------------------------------------------------
// Launch
// ---------------------------------------------------------------------------
extern "C" void kernel_launch(void* const* d_in, const int* in_sizes, int n_in,
                              void* d_out, int out_size)
{
    (void)in_sizes; (void)n_in; (void)out_size;
    const float* q  = (const float*)d_in[0];
    const float* k  = (const float*)d_in[1];
    const float* v  = (const float*)d_in[2];
    const unsigned char* mask = (const unsigned char*)d_in[3];
    const float* Wq = (const float*)d_in[4];
    const float* bq = (const float*)d_in[5];
    const float* Wk = (const float*)d_in[6];
    const float* bk = (const float*)d_in[7];
    const float* Wv = (const float*)d_in[8];
    const float* bv = (const float*)d_in[9];
    const float* Wo = (const float*)d_in[10];
    const float* bo = (const float*)d_in[11];

    float* out = (float*)d_out;
    float* top = out + (size_t)Bb * Ss * HID;   // top_attn region

    cudaFuncSetAttribute(k_flash, cudaFuncAttributeMaxDynamicSharedMemorySize,
                         FLASH_SMEM_BYTES);

    k_proj      <<<dim3(8, 64, 3), 256>>>(q, k, v, Wq, Wk, Wv, bq, bk, bv);
    k_vtrans    <<<dim3(32, 64), 256>>>();
    k_flash     <<<dim3(16, 64), 256, FLASH_SMEM_BYTES>>>(mask);
    k_scores_h0 <<<dim3(16, 16, 4), 256>>>(mask, top);
    k_softmax_h0<<<Bb * Ss, 256>>>(top);
    k_outproj   <<<dim3(8, 64), 256>>>(Wo, bo, out);
}

// round 16
// speedup vs baseline: 1.3508x; 1.0045x over previous
#include <cuda_runtime.h>
#include <cstdint>
#include <cstddef>

// Problem constants
constexpr int Bb  = 4;
constexpr int Ss  = 2048;
constexpr int HID = 1024;
constexpr int NH  = 16;
constexpr int HD  = 64;
constexpr float INV_SCALE = 0.125f;      // 1/sqrt(64)

// ---------------------------------------------------------------------------
// Scratch (static device globals — allocation-free at launch time)
// ---------------------------------------------------------------------------
__device__ float g_q  [(size_t)Bb * NH * Ss * HD];   // [b,h,s,d]
__device__ float g_k  [(size_t)Bb * NH * Ss * HD];
__device__ float g_v  [(size_t)Bb * NH * Ss * HD];
__device__ float g_vt [(size_t)Bb * NH * HD * Ss];   // [b,h,d,s]  (V transposed)
__device__ float g_ctx[(size_t)Bb * Ss * NH * HD];   // [b,s,h*64+d]

// ---------------------------------------------------------------------------
// tf32 MMA helpers
// ---------------------------------------------------------------------------
__device__ __forceinline__ uint32_t f2tf(float x)
{
    uint32_t u;
    asm("cvt.rna.tf32.f32 %0, %1;" : "=r"(u) : "f"(x));
    return u;
}

// D = A(16x8) * B(8x8) + D, tf32 inputs, f32 accum.
__device__ __forceinline__ void mma8(float* c,
                                     uint32_t a0, uint32_t a1, uint32_t a2, uint32_t a3,
                                     uint32_t b0, uint32_t b1)
{
    asm volatile(
        "mma.sync.aligned.m16n8k8.row.col.f32.tf32.tf32.f32 "
        "{%0,%1,%2,%3},{%4,%5,%6,%7},{%8,%9},{%0,%1,%2,%3};"
        : "+f"(c[0]), "+f"(c[1]), "+f"(c[2]), "+f"(c[3])
        : "r"(a0), "r"(a1), "r"(a2), "r"(a3), "r"(b0), "r"(b1));
}

// Legacy staging (k_proj / k_scores_h0 / k_outproj): rows x 32 tile, pad 36.
__device__ __forceinline__ void stage128(const float* __restrict__ g,
                                         int row0, int k0, int ld,
                                         uint32_t (*sm)[36], int tid)
{
#pragma unroll
    for (int p = 0; p < 4; ++p) {
        int id = tid + p * 256;
        int r  = id >> 3;
        int c4 = id & 7;
        const float4 f = *reinterpret_cast<const float4*>(
            g + (size_t)(row0 + r) * ld + k0 + c4 * 4);
        sm[r][c4 * 4 + 0] = f2tf(f.x);
        sm[r][c4 * 4 + 1] = f2tf(f.y);
        sm[r][c4 * 4 + 2] = f2tf(f.z);
        sm[r][c4 * 4 + 3] = f2tf(f.w);
    }
}

// Flash staging: ROWS x 64 tile, stride 72, k-columns permuted within each
// 8-group as [0,4,1,5,2,6,3,7] so fragment pairs (tq, tq+4) are adjacent
// (single LDS.64, conflict-free with stride ≡ 8 mod 32).
template<int ROWS>
__device__ __forceinline__ void stage_perm(const float* __restrict__ g,
                                           int row0, int ld,
                                           uint32_t (*sm)[72], int tid)
{
#pragma unroll
    for (int p = 0; p < ROWS / 16; ++p) {
        int id = tid + p * 256;
        int r  = id >> 4;                // 16 float4 per 64-wide row
        int c4 = id & 15;
        const float4 f = *reinterpret_cast<const float4*>(
            g + (size_t)(row0 + r) * ld + c4 * 4);
        const int base = ((4 * c4) & 56) + (c4 & 1);  // perm position of col 4*c4
        uint32_t* row = sm[r];
        row[base + 0] = f2tf(f.x);
        row[base + 2] = f2tf(f.y);
        row[base + 4] = f2tf(f.z);
        row[base + 6] = f2tf(f.w);
    }
}

// Core 128x128 NT tile compute (legacy kernels). As/Bs [128][36].
__device__ __forceinline__ void mma_chunk_128x128(const uint32_t (*As)[36],
                                                  const uint32_t (*Bs)[36],
                                                  float c[2][8][4],
                                                  int wm, int wn, int g, int tq)
{
#pragma unroll
    for (int ks = 0; ks < 4; ++ks) {
        const int k8 = ks * 8;
        uint32_t a[2][4];
#pragma unroll
        for (int im = 0; im < 2; ++im) {
            const int m = wm + im * 16;
            a[im][0] = As[m + g    ][k8 + tq    ];
            a[im][1] = As[m + g + 8][k8 + tq    ];
            a[im][2] = As[m + g    ][k8 + tq + 4];
            a[im][3] = As[m + g + 8][k8 + tq + 4];
        }
#pragma unroll
        for (int jn = 0; jn < 8; ++jn) {
            const int n = wn + jn * 8;
            const uint32_t b0 = Bs[n + g][k8 + tq    ];
            const uint32_t b1 = Bs[n + g][k8 + tq + 4];
            mma8(c[0][jn], a[0][0], a[0][1], a[0][2], a[0][3], b0, b1);
            mma8(c[1][jn], a[1][0], a[1][1], a[1][2], a[1][3], b0, b1);
        }
    }
}

// Fast exp on the FMA pipe (x <= 0 in softmax; rel err ~2e-5).
__device__ __forceinline__ float fast_exp(float x)
{
    float t  = fmaxf(x * 1.4426950408889634f, -126.0f);
    float fi = floorf(t);
    float f  = t - fi;
    float p = 1.5357550e-4f;
    p = fmaf(p, f, 1.3333558e-3f);
    p = fmaf(p, f, 9.6181291e-3f);
    p = fmaf(p, f, 5.5504109e-2f);
    p = fmaf(p, f, 2.4022651e-1f);
    p = fmaf(p, f, 6.9314718e-1f);
    p = fmaf(p, f, 1.0f);
    return __int_as_float(((int)fi + 127) << 23) * p;
}

// ---------------------------------------------------------------------------
// Kernel 1: fused QKV projection.  y[b,h,s,d] = x @ W^T + bias
// grid (8, 64, 3), block 256
// ---------------------------------------------------------------------------
__global__ void __launch_bounds__(256, 2)
k_proj(const float* __restrict__ xq, const float* __restrict__ xk,
       const float* __restrict__ xv,
       const float* __restrict__ Wq, const float* __restrict__ Wk,
       const float* __restrict__ Wv,
       const float* __restrict__ bq, const float* __restrict__ bk,
       const float* __restrict__ bv)
{
    __shared__ uint32_t As[128][36];
    __shared__ uint32_t Bs[128][36];

    const int z = blockIdx.z;
    const float* A    = (z == 0) ? xq : (z == 1) ? xk : xv;
    const float* W    = (z == 0) ? Wq : (z == 1) ? Wk : Wv;
    const float* bias = (z == 0) ? bq : (z == 1) ? bk : bv;
    float* out        = (z == 0) ? g_q : (z == 1) ? g_k : g_v;

    const int m0 = blockIdx.y * 128;
    const int n0 = blockIdx.x * 128;
    const int tid  = threadIdx.x;
    const int lane = tid & 31, warp = tid >> 5;
    const int wm = (warp & 3) * 32, wn = (warp >> 2) * 64;
    const int g = lane >> 2, tq = lane & 3;

    float c[2][8][4];
#pragma unroll
    for (int i = 0; i < 2; ++i)
#pragma unroll
        for (int j = 0; j < 8; ++j)
#pragma unroll
            for (int r = 0; r < 4; ++r) c[i][j][r] = 0.f;

    for (int k0 = 0; k0 < HID; k0 += 32) {
        stage128(A, m0, k0, HID, As, tid);
        stage128(W, n0, k0, HID, Bs, tid);
        __syncthreads();
        mma_chunk_128x128(As, Bs, c, wm, wn, g, tq);
        __syncthreads();
    }

#pragma unroll
    for (int jn = 0; jn < 8; ++jn) {
        const int n = n0 + wn + jn * 8 + 2 * tq;
        const int h = n >> 6, d = n & 63;
        const float bx = bias[n], by = bias[n + 1];
#pragma unroll
        for (int im = 0; im < 2; ++im) {
            const int m = m0 + wm + im * 16 + g;
            {
                const int bi = m >> 11, s = m & 2047;
                float2 v = { c[im][jn][0] + bx, c[im][jn][1] + by };
                *reinterpret_cast<float2*>(
                    out + (((size_t)(bi * NH + h)) * Ss + s) * HD + d) = v;
            }
            {
                const int m2 = m + 8;
                const int bi = m2 >> 11, s = m2 & 2047;
                float2 v = { c[im][jn][2] + bx, c[im][jn][3] + by };
                *reinterpret_cast<float2*>(
                    out + (((size_t)(bi * NH + h)) * Ss + s) * HD + d) = v;
            }
        }
    }
}

// ---------------------------------------------------------------------------
// Kernel 2: V transpose  g_v[b,h,s,d] -> g_vt[b,h,d,s]
// grid (32, 64), block 256
// ---------------------------------------------------------------------------
__global__ void __launch_bounds__(256)
k_vtrans()
{
    __shared__ float T[64][65];
    const int bh = blockIdx.y;
    const int s0 = blockIdx.x * 64;
    const float* src = g_v + ((size_t)bh * Ss + s0) * HD;
    const int tid = threadIdx.x;

#pragma unroll
    for (int p = 0; p < 4; ++p) {
        int id = tid + p * 256;
        int r  = id >> 4, c4 = id & 15;
        float4 f = *reinterpret_cast<const float4*>(src + (size_t)r * HD + c4 * 4);
        T[r][c4 * 4 + 0] = f.x; T[r][c4 * 4 + 1] = f.y;
        T[r][c4 * 4 + 2] = f.z; T[r][c4 * 4 + 3] = f.w;
    }
    __syncthreads();

    float* dst = g_vt + (size_t)bh * HD * Ss + s0;
#pragma unroll
    for (int p = 0; p < 4; ++p) {
        int id = tid + p * 256;
        int d  = id >> 4, c4 = id & 15;
        float4 o;
        o.x = T[c4 * 4 + 0][d]; o.y = T[c4 * 4 + 1][d];
        o.z = T[c4 * 4 + 2][d]; o.w = T[c4 * 4 + 3][d];
        *reinterpret_cast<float4*>(dst + (size_t)d * Ss + c4 * 4) = o;
    }
}

// ---------------------------------------------------------------------------
// Kernel 3: flash attention (scores+softmax+context fused), all 64 bh.
// grid (16 q-tiles, 64 bh), block 256 (8 warps, warp tile 16x64).
// Dynamic smem: Qs[128][72] Ks[64][72] Vt[64][72] Ps[128][72] = 110592 B.
// ---------------------------------------------------------------------------
constexpr int FLASH_SMEM_BYTES = (9216 + 4608 + 4608 + 9216) * 4;

__global__ void __launch_bounds__(256, 2)
k_flash(const unsigned char* __restrict__ mask)
{
    extern __shared__ uint32_t smemw[];
    uint32_t (*Qs)[72] = reinterpret_cast<uint32_t(*)[72]>(smemw);
    uint32_t (*Ks)[72] = reinterpret_cast<uint32_t(*)[72]>(smemw + 9216);
    uint32_t (*Vt)[72] = reinterpret_cast<uint32_t(*)[72]>(smemw + 13824);
    uint32_t (*Ps)[72] = reinterpret_cast<uint32_t(*)[72]>(smemw + 18432);

    const int bh = blockIdx.y;
    const int bi = bh >> 4, h = bh & 15;
    const int m0 = blockIdx.x * 128;
    const float* Q  = g_q  + (size_t)bh * Ss * HD;
    const float* K  = g_k  + (size_t)bh * Ss * HD;
    const float* VT = g_vt + (size_t)bh * HD * Ss;

    const int tid  = threadIdx.x;
    const int lane = tid & 31, warp = tid >> 5;
    const int wm = warp * 16;
    const int g = lane >> 2, tq = lane & 3;
    // permuted positions of kv-columns 2tq and 2tq+1 within an 8-group
    const int pe = ((2 * tq) & 3) * 2 + ((2 * tq) >> 2);
    const int po = ((2 * tq + 1) & 3) * 2 + ((2 * tq + 1) >> 2);

    stage_perm<128>(Q, m0, HD, Qs, tid);

    float co[8][4];
#pragma unroll
    for (int j = 0; j < 8; ++j)
#pragma unroll
        for (int r = 0; r < 4; ++r) co[j][r] = 0.f;
    float mr0 = -3.0e38f, mr1 = -3.0e38f, lr0 = 0.f, lr1 = 0.f;

    const unsigned char* mbase0 =
        mask + ((size_t)bi * Ss + (m0 + wm + g)) * Ss;
    const unsigned char* mbase1 = mbase0 + (size_t)8 * Ss;

    for (int it = 0; it < Ss / 64; ++it) {
        const int kv0 = it * 64;
        __syncthreads();                       // prev PV reads done
        stage_perm<64>(K, kv0, HD, Ks, tid);
        stage_perm<64>(VT + kv0, 0, Ss, Vt, tid);
        __syncthreads();

        // ---- S = Q K^T over this kv tile ----
        float cs[8][4];
#pragma unroll
        for (int j = 0; j < 8; ++j)
#pragma unroll
            for (int r = 0; r < 4; ++r) cs[j][r] = 0.f;

#pragma unroll
        for (int ks = 0; ks < 8; ++ks) {
            const int kp = ks * 8 + 2 * tq;
            const uint2 a0 = *reinterpret_cast<const uint2*>(&Qs[wm + g    ][kp]);
            const uint2 a1 = *reinterpret_cast<const uint2*>(&Qs[wm + g + 8][kp]);
#pragma unroll
            for (int jn = 0; jn < 8; ++jn) {
                const uint2 bb = *reinterpret_cast<const uint2*>(&Ks[jn * 8 + g][kp]);
                mma8(cs[jn], a0.x, a1.x, a0.y, a1.y, bb.x, bb.y);
            }
        }

        // ---- scale + mask + row max ----
        float mx0 = -3.0e38f, mx1 = -3.0e38f;
#pragma unroll
        for (int jn = 0; jn < 8; ++jn) {
            const int n = kv0 + jn * 8 + 2 * tq;
            const uchar2 u0 = *reinterpret_cast<const uchar2*>(mbase0 + n);
            const uchar2 u1 = *reinterpret_cast<const uchar2*>(mbase1 + n);
            float v0 = cs[jn][0] * INV_SCALE; if (u0.x) v0 = -1e9f;
            float v1 = cs[jn][1] * INV_SCALE; if (u0.y) v1 = -1e9f;
            float v2 = cs[jn][2] * INV_SCALE; if (u1.x) v2 = -1e9f;
            float v3 = cs[jn][3] * INV_SCALE; if (u1.y) v3 = -1e9f;
            cs[jn][0] = v0; cs[jn][1] = v1; cs[jn][2] = v2; cs[jn][3] = v3;
            mx0 = fmaxf(mx0, fmaxf(v0, v1));
            mx1 = fmaxf(mx1, fmaxf(v2, v3));
        }
        mx0 = fmaxf(mx0, __shfl_xor_sync(0xffffffffu, mx0, 1));
        mx0 = fmaxf(mx0, __shfl_xor_sync(0xffffffffu, mx0, 2));
        mx1 = fmaxf(mx1, __shfl_xor_sync(0xffffffffu, mx1, 1));
        mx1 = fmaxf(mx1, __shfl_xor_sync(0xffffffffu, mx1, 2));

        const float mn0 = fmaxf(mr0, mx0), mn1 = fmaxf(mr1, mx1);
        const float al0 = fast_exp(mr0 - mn0), al1 = fast_exp(mr1 - mn1);
        mr0 = mn0; mr1 = mn1;

        // ---- P = exp(S - m), store permuted to smem; rescale O ----
        float s0 = 0.f, s1 = 0.f;
#pragma unroll
        for (int jn = 0; jn < 8; ++jn) {
            const float p0 = fast_exp(cs[jn][0] - mn0);
            const float p1 = fast_exp(cs[jn][1] - mn0);
            const float p2 = fast_exp(cs[jn][2] - mn1);
            const float p3 = fast_exp(cs[jn][3] - mn1);
            s0 += p0 + p1; s1 += p2 + p3;
            uint32_t* r0 = Ps[wm + g    ] + jn * 8;
            uint32_t* r1 = Ps[wm + g + 8] + jn * 8;
            r0[pe] = f2tf(p0); r0[po] = f2tf(p1);
            r1[pe] = f2tf(p2); r1[po] = f2tf(p3);
            co[jn][0] *= al0; co[jn][1] *= al0;
            co[jn][2] *= al1; co[jn][3] *= al1;
        }
        s0 += __shfl_xor_sync(0xffffffffu, s0, 1);
        s0 += __shfl_xor_sync(0xffffffffu, s0, 2);
        s1 += __shfl_xor_sync(0xffffffffu, s1, 1);
        s1 += __shfl_xor_sync(0xffffffffu, s1, 2);
        lr0 = lr0 * al0 + s0;
        lr1 = lr1 * al1 + s1;

        __syncwarp();   // P rows are warp-private; smem visibility within warp

        // ---- O += P V ----
#pragma unroll
        for (int ks = 0; ks < 8; ++ks) {
            const int kp = ks * 8 + 2 * tq;
            const uint2 a0 = *reinterpret_cast<const uint2*>(&Ps[wm + g    ][kp]);
            const uint2 a1 = *reinterpret_cast<const uint2*>(&Ps[wm + g + 8][kp]);
#pragma unroll
            for (int jn = 0; jn < 8; ++jn) {
                const uint2 bb = *reinterpret_cast<const uint2*>(&Vt[jn * 8 + g][kp]);
                mma8(co[jn], a0.x, a1.x, a0.y, a1.y, bb.x, bb.y);
            }
        }
    }

    // ---- finalize: O /= l, write to g_ctx ----
    const float i0 = 1.f / lr0, i1 = 1.f / lr1;
    float* C0 = g_ctx + ((size_t)(bi * Ss + m0 + wm + g)) * (NH * HD) + h * HD;
    float* C1 = C0 + (size_t)8 * (NH * HD);
#pragma unroll
    for (int jn = 0; jn < 8; ++jn) {
        const int d = jn * 8 + 2 * tq;
        *reinterpret_cast<float2*>(C0 + d) =
            make_float2(co[jn][0] * i0, co[jn][1] * i0);
        *reinterpret_cast<float2*>(C1 + d) =
            make_float2(co[jn][2] * i1, co[jn][3] * i1);
    }
}

// ---------------------------------------------------------------------------
// Kernel 4: head-0 scores -> top buffer (raw, scaled+masked)
// grid (16, 16, 4), block 256
// ---------------------------------------------------------------------------
__global__ void __launch_bounds__(256, 2)
k_scores_h0(const unsigned char* __restrict__ mask, float* __restrict__ topbase)
{
    __shared__ uint32_t As[128][36];
    __shared__ uint32_t Bs[128][36];

    const int bi = blockIdx.z;
    const int bh = bi * NH;                 // head 0 of batch bi
    const float* Q = g_q + (size_t)bh * Ss * HD;
    const float* K = g_k + (size_t)bh * Ss * HD;
    float* Sout    = topbase + (size_t)bi * Ss * Ss;

    const int m0 = blockIdx.y * 128;
    const int n0 = blockIdx.x * 128;
    const int tid  = threadIdx.x;
    const int lane = tid & 31, warp = tid >> 5;
    const int wm = (warp & 3) * 32, wn = (warp >> 2) * 64;
    const int g = lane >> 2, tq = lane & 3;

    float c[2][8][4];
#pragma unroll
    for (int i = 0; i < 2; ++i)
#pragma unroll
        for (int j = 0; j < 8; ++j)
#pragma unroll
            for (int r = 0; r < 4; ++r) c[i][j][r] = 0.f;

#pragma unroll
    for (int k0 = 0; k0 < HD; k0 += 32) {
        stage128(Q, m0, k0, HD, As, tid);
        stage128(K, n0, k0, HD, Bs, tid);
        __syncthreads();
        mma_chunk_128x128(As, Bs, c, wm, wn, g, tq);
        __syncthreads();
    }

#pragma unroll
    for (int jn = 0; jn < 8; ++jn) {
        const int n = n0 + wn + jn * 8 + 2 * tq;
#pragma unroll
        for (int im = 0; im < 2; ++im) {
#pragma unroll
            for (int rr = 0; rr < 2; ++rr) {
                const int m = m0 + wm + im * 16 + g + rr * 8;
                const size_t mrow = (size_t)(bi * Ss + m) * Ss + n;
                float v0 = c[im][jn][rr * 2 + 0] * INV_SCALE;
                float v1 = c[im][jn][rr * 2 + 1] * INV_SCALE;
                if (mask[mrow])     v0 = -1e9f;
                if (mask[mrow + 1]) v1 = -1e9f;
                *reinterpret_cast<float2*>(Sout + (size_t)m * Ss + n) =
                    make_float2(v0, v1);
            }
        }
    }
}

// ---------------------------------------------------------------------------
// Kernel 5: softmax in place over top buffer rows (4*2048 rows)
// ---------------------------------------------------------------------------
__global__ void __launch_bounds__(256)
k_softmax_h0(float* __restrict__ top)
{
    const size_t row = blockIdx.x;
    float* p = top + row * Ss;
    const int tid = threadIdx.x;

    float4* p4 = reinterpret_cast<float4*>(p);
    float4 v0 = p4[tid];
    float4 v1 = p4[tid + 256];

    float mx = fmaxf(fmaxf(fmaxf(v0.x, v0.y), fmaxf(v0.z, v0.w)),
                     fmaxf(fmaxf(v1.x, v1.y), fmaxf(v1.z, v1.w)));
#pragma unroll
    for (int o = 16; o > 0; o >>= 1)
        mx = fmaxf(mx, __shfl_xor_sync(0xffffffffu, mx, o));

    __shared__ float smax[8];
    __shared__ float ssum[8];
    if ((tid & 31) == 0) smax[tid >> 5] = mx;
    __syncthreads();
    float bm = smax[0];
#pragma unroll
    for (int i = 1; i < 8; ++i) bm = fmaxf(bm, smax[i]);

    v0.x = fast_exp(v0.x - bm); v0.y = fast_exp(v0.y - bm);
    v0.z = fast_exp(v0.z - bm); v0.w = fast_exp(v0.w - bm);
    v1.x = fast_exp(v1.x - bm); v1.y = fast_exp(v1.y - bm);
    v1.z = fast_exp(v1.z - bm); v1.w = fast_exp(v1.w - bm);

    float s = (v0.x + v0.y) + (v0.z + v0.w) + (v1.x + v1.y) + (v1.z + v1.w);
#pragma unroll
    for (int o = 16; o > 0; o >>= 1)
        s += __shfl_xor_sync(0xffffffffu, s, o);
    if ((tid & 31) == 0) ssum[tid >> 5] = s;
    __syncthreads();
    float tot = 0.f;
#pragma unroll
    for (int i = 0; i < 8; ++i) tot += ssum[i];
    const float inv = 1.0f / tot;

    v0.x *= inv; v0.y *= inv; v0.z *= inv; v0.w *= inv;
    v1.x *= inv; v1.y *= inv; v1.z *= inv; v1.w *= inv;

    p4[tid]       = v0;
    p4[tid + 256] = v1;
}

// ---------------------------------------------------------------------------
// Kernel 6: output = ctx @ W_o^T + b_o  -> d_out[0 : B*S*HID)
// grid (8, 64), block 256
// ---------------------------------------------------------------------------
__global__ void __launch_bounds__(256, 2)
k_outproj(const float* __restrict__ Wo, const float* __restrict__ bo,
          float* __restrict__ out)
{
    __shared__ uint32_t As[128][36];
    __shared__ uint32_t Bs[128][36];

    const int m0 = blockIdx.y * 128;
    const int n0 = blockIdx.x * 128;
    const int tid  = threadIdx.x;
    const int lane = tid & 31, warp = tid >> 5;
    const int wm = (warp & 3) * 32, wn = (warp >> 2) * 64;
    const int g = lane >> 2, tq = lane & 3;

    float c[2][8][4];
#pragma unroll
    for (int i = 0; i < 2; ++i)
#pragma unroll
        for (int j = 0; j < 8; ++j)
#pragma unroll
            for (int r = 0; r < 4; ++r) c[i][j][r] = 0.f;

    for (int k0 = 0; k0 < NH * HD; k0 += 32) {
        stage128(g_ctx, m0, k0, NH * HD, As, tid);
        stage128(Wo,   n0, k0, NH * HD, Bs, tid);
        __syncthreads();
        mma_chunk_128x128(As, Bs, c, wm, wn, g, tq);
        __syncthreads();
    }

#pragma unroll
    for (int jn = 0; jn < 8; ++jn) {
        const int n = n0 + wn + jn * 8 + 2 * tq;
        const float bx = bo[n], by = bo[n + 1];
#pragma unroll
        for (int im = 0; im < 2; ++im) {
#pragma unroll
            for (int rr = 0; rr < 2; ++rr) {
                const int m = m0 + wm + im * 16 + g + rr * 8;
                *reinterpret_cast<float2*>(out + (size_t)m * HID + n) =
                    make_float2(c[im][jn][rr * 2] + bx, c[im][jn][rr * 2 + 1] + by);
            }
        }
    }
}

// ---------------------------------------------------------------------------
// Launch
// ---------------------------------------------------------------------------
extern "C" void kernel_launch(void* const* d_in, const int* in_sizes, int n_in,
                              void* d_out, int out_size)
{
    (void)in_sizes; (void)n_in; (void)out_size;
    const float* q  = (const float*)d_in[0];
    const float* k  = (const float*)d_in[1];
    const float* v  = (const float*)d_in[2];
    const unsigned char* mask = (const unsigned char*)d_in[3];
    const float* Wq = (const float*)d_in[4];
    const float* bq = (const float*)d_in[5];
    const float* Wk = (const float*)d_in[6];
    const float* bk = (const float*)d_in[7];
    const float* Wv = (const float*)d_in[8];
    const float* bv = (const float*)d_in[9];
    const float* Wo = (const float*)d_in[10];
    const float* bo = (const float*)d_in[11];

    float* out = (float*)d_out;
    float* top = out + (size_t)Bb * Ss * HID;   // top_attn region

    cudaFuncSetAttribute(k_flash, cudaFuncAttributeMaxDynamicSharedMemorySize,
                         FLASH_SMEM_BYTES);

    k_proj      <<<dim3(8, 64, 3), 256>>>(q, k, v, Wq, Wk, Wv, bq, bk, bv);
    k_vtrans    <<<dim3(32, 64), 256>>>();
    k_flash     <<<dim3(16, 64), 256, FLASH_SMEM_BYTES>>>(mask);
    k_scores_h0 <<<dim3(16, 16, 4), 256>>>(mask, top);
    k_softmax_h0<<<Bb * Ss, 256>>>(top);
    k_outproj   <<<dim3(8, 64), 256>>>(Wo, bo, out);
}